// round 7
// baseline (speedup 1.0000x reference)
#include <cuda_runtime.h>
#include <cuda_fp16.h>
#include <cstdint>
#include <math.h>
#include <mma.h>
using namespace nvcuda;

#define N_NODES 20000
#define M_PAD 20096              // N_NODES padded to 128
#define N_EDGES 256000
#define ET (N_EDGES + N_NODES)   // with self loops = 276000
#define N_GRAPHS 512
#define F_IN 75
#define KP1 96                   // padded F_IN (mult of 32 for BK=32)
#define HEADS 10
#define HF 750
#define NP1 768                  // padded HF (also K of gemm2)
#define NP1_2 (NP1 / 2)          // 384 half2
#define OUT_DIM 128

#define SCAN_B 256
#define NBLK ((N_NODES + SCAN_B - 1) / SCAN_B)   // 79

// ---------------- scratch ---------------------------------------------------
__device__ __align__(256) __half g_xh[(size_t)M_PAD * KP1];
__device__ __align__(256) __half g_W1h[KP1 * NP1];
__device__ __align__(256) __half g_W2h[NP1 * OUT_DIM];
__device__ __align__(256) __half g_h1h[(size_t)M_PAD * NP1];
__device__ __align__(256) __half g_out1h[(size_t)M_PAD * NP1];
__device__ __align__(256) __half g_h2h[(size_t)M_PAD * OUT_DIM];
__device__ float g_was1[F_IN * HEADS];
__device__ float g_wad1[F_IN * HEADS];
__device__ float g_as1[N_NODES * HEADS];
__device__ float g_ad1[N_NODES * HEADS];
__device__ float g_as2[N_NODES];
__device__ float g_ad2[N_NODES];
__device__ int   g_deg[N_NODES];
__device__ int   g_bsum[NBLK];
__device__ int   g_boff[NBLK];
__device__ int   g_rowptr[N_NODES + 1];
__device__ int   g_cur[N_NODES];
__device__ int   g_col[ET];
__device__ float g_pool[N_GRAPHS * OUT_DIM];

// ---------------- helpers ---------------------------------------------------
__device__ __forceinline__ void edge_sd(const int* __restrict__ ei, int e,
                                        int& s, int& d) {
    if (e < N_EDGES) { s = ei[e]; d = ei[N_EDGES + e]; }
    else             { s = e - N_EDGES; d = s; }
}
__device__ __forceinline__ float leaky(float x) { return x > 0.f ? x : 0.2f * x; }

__device__ __forceinline__ void cp16(void* s, const void* g) {
    unsigned int sa = (unsigned int)__cvta_generic_to_shared(s);
    asm volatile("cp.async.cg.shared.global [%0], [%1], 16;\n" :: "r"(sa), "l"(g));
}
#define CP_COMMIT() asm volatile("cp.async.commit_group;\n" ::: "memory")
#define CP_WAIT1()  asm volatile("cp.async.wait_group 1;\n" ::: "memory")
#define CP_WAIT0()  asm volatile("cp.async.wait_group 0;\n" ::: "memory")

// ---------------- fused pad / convert / zero ---------------------------------
__global__ void pad_all(const float* __restrict__ x,
                        const float* __restrict__ W1,
                        const float* __restrict__ W2) {
    const int S0 = M_PAD * KP1;
    const int S1 = KP1 * NP1;
    const int S2 = NP1 * OUT_DIM;
    const int S3 = N_NODES;
    const int S4 = N_GRAPHS * OUT_DIM;
    int t = blockIdx.x * blockDim.x + threadIdx.x;
    if (t < S0) {
        int n = t / KP1, k = t - n * KP1;
        g_xh[t] = __float2half((n < N_NODES && k < F_IN) ? x[n * F_IN + k] : 0.f);
        return;
    }
    t -= S0;
    if (t < S1) {
        int k = t / NP1, n = t - k * NP1;
        g_W1h[t] = __float2half((k < F_IN && n < HF) ? W1[k * HF + n] : 0.f);
        return;
    }
    t -= S1;
    if (t < S2) {
        int k = t / OUT_DIM, n = t - k * OUT_DIM;
        g_W2h[t] = __float2half((k < HF) ? W2[k * OUT_DIM + n] : 0.f);
        return;
    }
    t -= S2;
    if (t < S3) { g_deg[t] = 0; return; }
    t -= S3;
    if (t < S4) g_pool[t] = 0.f;
}
#define PAD_TOTAL (M_PAD * KP1 + KP1 * NP1 + NP1 * OUT_DIM + N_NODES + N_GRAPHS * OUT_DIM)

// ---------------- CSR build (multi-block scan) -------------------------------
__global__ void deg_count(const int* __restrict__ ei) {
    int e = blockIdx.x * blockDim.x + threadIdx.x;
    if (e >= ET) return;
    int s, d; edge_sd(ei, e, s, d);
    atomicAdd(&g_deg[d], 1);
}
__global__ __launch_bounds__(SCAN_B) void scan_part() {
    __shared__ int red[SCAN_B / 32];
    int b = blockIdx.x, tid = threadIdx.x;
    int idx = b * SCAN_B + tid;
    int v = (idx < N_NODES) ? g_deg[idx] : 0;
    #pragma unroll
    for (int o = 16; o > 0; o >>= 1) v += __shfl_down_sync(~0u, v, o);
    if ((tid & 31) == 0) red[tid >> 5] = v;
    __syncthreads();
    if (tid < SCAN_B / 32) {
        int s = red[tid];
        #pragma unroll
        for (int o = SCAN_B / 64; o > 0; o >>= 1) s += __shfl_down_sync(~0u, s, o);
        if (tid == 0) g_bsum[b] = s;
    }
}
__global__ __launch_bounds__(128) void scan_top() {
    __shared__ int sh[NBLK];
    int tid = threadIdx.x;
    if (tid < NBLK) sh[tid] = g_bsum[tid];
    __syncthreads();
    if (tid == 0) {
        int run = 0;
        for (int i = 0; i < NBLK; i++) { g_boff[i] = run; run += sh[i]; }
        g_rowptr[N_NODES] = ET;
    }
}
__global__ __launch_bounds__(SCAN_B) void scan_down() {
    __shared__ int sh[SCAN_B];
    int b = blockIdx.x, tid = threadIdx.x;
    int idx = b * SCAN_B + tid;
    int v = (idx < N_NODES) ? g_deg[idx] : 0;
    sh[tid] = v;
    __syncthreads();
    for (int off = 1; off < SCAN_B; off <<= 1) {
        int t = (tid >= off) ? sh[tid - off] : 0;
        __syncthreads();
        sh[tid] += t;
        __syncthreads();
    }
    if (idx < N_NODES) {
        int excl = sh[tid] - v + g_boff[b];
        g_rowptr[idx] = excl;
        g_cur[idx] = excl;
    }
}
__global__ void scatter_ids(const int* __restrict__ ei) {
    int e = blockIdx.x * blockDim.x + threadIdx.x;
    if (e >= ET) return;
    int s, d; edge_sd(ei, e, s, d);
    int pos = atomicAdd(&g_cur[d], 1);
    g_col[pos] = s;
}

// ---------------- fp16 tensor-core GEMM with cp.async double buffer ----------
// C[M,N] = A[M,K] @ B[K,N]; 128x128 block tile, BK=32, 8 warps of 64x32.
// M%128==0, N%128==0, K%32==0.
#define TBM 128
#define TBN 128
#define TBK 32
#define GA_LD 40    // 32 + 8 pad halves  (80B row stride)
#define GB_LD 136   // 128 + 8 pad halves (272B row stride)
#define A_ST (TBM * GA_LD)          // 5120 halves
#define B_ST (TBK * GB_LD)          // 4352 halves
#define STAGE (A_ST + B_ST)         // 9472 halves = 18944 B

__global__ __launch_bounds__(256) void gemm_h(
    const __half* __restrict__ A, const __half* __restrict__ B,
    __half* __restrict__ C, int M, int N, int K) {
    __shared__ __align__(32) __half sm[2 * STAGE];   // 37888 B
    int bm = blockIdx.y * TBM, bn = blockIdx.x * TBN;
    int tid = threadIdx.x, warp = tid >> 5, lane = tid & 31;
    int wm = (warp >> 2) * 64, wn = (warp & 3) * 32;

    wmma::fragment<wmma::accumulator, 16, 16, 16, float> acc[4][2];
    #pragma unroll
    for (int i = 0; i < 4; i++)
        #pragma unroll
        for (int j = 0; j < 2; j++)
            wmma::fill_fragment(acc[i][j], 0.f);

    // stage loader: A tile 128x32 (512 16B chunks), B tile 32x128 (512 chunks)
    auto load_stage = [&](int s, int k0) {
        __half* As = sm + s * STAGE;
        __half* Bs = sm + s * STAGE + A_ST;
        #pragma unroll
        for (int t = 0; t < 2; t++) {
            int c = t * 256 + tid;
            int r = c >> 2, q = c & 3;                 // 4 chunks per A row
            cp16(As + r * GA_LD + q * 8,
                 A + (size_t)(bm + r) * K + k0 + q * 8);
        }
        #pragma unroll
        for (int t = 0; t < 2; t++) {
            int c = t * 256 + tid;
            int r = c >> 4, q = c & 15;                // 16 chunks per B row
            cp16(Bs + r * GB_LD + q * 8,
                 B + (size_t)(k0 + r) * N + bn + q * 8);
        }
    };

    int nk = K / TBK;
    load_stage(0, 0);
    CP_COMMIT();
    for (int kt = 0; kt < nk; kt++) {
        int s = kt & 1;
        if (kt + 1 < nk) {
            load_stage(s ^ 1, (kt + 1) * TBK);
            CP_COMMIT();
            CP_WAIT1();
        } else {
            CP_WAIT0();
        }
        __syncthreads();
        const __half* As = sm + s * STAGE;
        const __half* Bs = sm + s * STAGE + A_ST;
        #pragma unroll
        for (int ks = 0; ks < 2; ks++) {
            wmma::fragment<wmma::matrix_a, 16, 16, 16, __half, wmma::row_major> af[4];
            wmma::fragment<wmma::matrix_b, 16, 16, 16, __half, wmma::row_major> bf[2];
            #pragma unroll
            for (int i = 0; i < 4; i++)
                wmma::load_matrix_sync(af[i],
                    As + (wm + i * 16) * GA_LD + ks * 16, GA_LD);
            #pragma unroll
            for (int j = 0; j < 2; j++)
                wmma::load_matrix_sync(bf[j],
                    Bs + ks * 16 * GB_LD + wn + j * 16, GB_LD);
            #pragma unroll
            for (int i = 0; i < 4; i++)
                #pragma unroll
                for (int j = 0; j < 2; j++)
                    wmma::mma_sync(acc[i][j], af[i], bf[j], acc[i][j]);
        }
        __syncthreads();
    }

    // epilogue: per-warp 16x20 fp32 staging (reuses pipeline smem), half2 out
    float* pb = (float*)sm + warp * (16 * 20);
    #pragma unroll
    for (int i = 0; i < 4; i++)
        #pragma unroll
        for (int j = 0; j < 2; j++) {
            wmma::store_matrix_sync(pb, acc[i][j], 20, wmma::mem_row_major);
            __syncwarp();
            int r = lane >> 1, off = (lane & 1) * 8;
            __half2* dst = (__half2*)(C + (size_t)(bm + wm + i * 16 + r) * N
                                      + bn + wn + j * 16 + off);
            const float* src = pb + r * 20 + off;
            #pragma unroll
            for (int t = 0; t < 4; t++)
                dst[t] = __floats2half2_rn(src[t * 2], src[t * 2 + 1]);
            __syncwarp();
        }
}

// ---------------- folded attention weights (layer 1) -------------------------
__global__ void attw1_kernel(const float* __restrict__ W1,
                             const float* __restrict__ a_src,
                             const float* __restrict__ a_dst) {
    int t = blockIdx.x * blockDim.x + threadIdx.x;
    if (t >= F_IN * HEADS) return;
    int k = t / HEADS, h = t - k * HEADS;
    const float* wrow = W1 + (size_t)k * HF + h * F_IN;
    const float* as = a_src + h * F_IN;
    const float* ad = a_dst + h * F_IN;
    float s = 0.f, d = 0.f;
    #pragma unroll 5
    for (int f = 0; f < F_IN; f++) { s += wrow[f] * as[f]; d += wrow[f] * ad[f]; }
    g_was1[k * HEADS + h] = s;
    g_wad1[k * HEADS + h] = d;
}
__global__ __launch_bounds__(256) void alpha1_kernel(const float* __restrict__ x) {
    __shared__ float ws[F_IN * HEADS], wd[F_IN * HEADS];
    int tid = threadIdx.x;
    for (int i = tid; i < F_IN * HEADS; i += 256) { ws[i] = g_was1[i]; wd[i] = g_wad1[i]; }
    __syncthreads();
    int t = blockIdx.x * 256 + tid;
    if (t >= N_NODES * HEADS) return;
    int n = t / HEADS, h = t - n * HEADS;
    const float* xr = x + (size_t)n * F_IN;
    float s = 0.f, d = 0.f;
    #pragma unroll 5
    for (int k = 0; k < F_IN; k++) {
        float xv = xr[k];
        s += xv * ws[k * HEADS + h];
        d += xv * wd[k * HEADS + h];
    }
    g_as1[t] = s;
    g_ad1[t] = d;
}

__global__ void alpha2_kernel(const float* __restrict__ a_src,
                              const float* __restrict__ a_dst) {
    int warp = (blockIdx.x * blockDim.x + threadIdx.x) >> 5;
    int lane = threadIdx.x & 31;
    if (warp >= N_NODES) return;
    const __half* row = g_h2h + (size_t)warp * OUT_DIM;
    float s = 0.f, d = 0.f;
    #pragma unroll
    for (int f = lane; f < OUT_DIM; f += 32) {
        float v = __half2float(row[f]);
        s += v * a_src[f];
        d += v * a_dst[f];
    }
    #pragma unroll
    for (int o = 16; o > 0; o >>= 1) {
        s += __shfl_down_sync(~0u, s, o);
        d += __shfl_down_sync(~0u, d, o);
    }
    if (lane == 0) { g_as2[warp] = s; g_ad2[warp] = d; }
}

// ---------------- layer-1 aggregation (fp16 gather, fp32 accum) --------------
#define CAP1 64
__global__ __launch_bounds__(192) void agg1_kernel(const float* __restrict__ b1) {
    int d = blockIdx.x;
    int tid = threadIdx.x;
    __shared__ int   csm[CAP1];
    __shared__ float wsm[CAP1 * HEADS];
    __shared__ float den[HEADS];
    __shared__ float adc[HEADS];
    if (tid < HEADS) {
        adc[tid] = g_ad1[d * HEADS + tid];
        den[tid] = 0.f;
    }
    int i0 = tid, i1 = tid + 192;
    int c0 = 2 * i0, c1 = 2 * i1;
    int h00 = min(c0 / F_IN, HEADS - 1), h01 = min((c0 + 1) / F_IN, HEADS - 1);
    int h10 = min(c1 / F_IN, HEADS - 1), h11 = min((c1 + 1) / F_IN, HEADS - 1);
    const __half2* H1 = (const __half2*)g_h1h;

    int start = g_rowptr[d], end = g_rowptr[d + 1];
    float2 acc0 = {0.f, 0.f}, acc1 = {0.f, 0.f};
    for (int p = start; p < end; p += CAP1) {
        int nc = min(CAP1, end - p);
        __syncthreads();
        if (tid < nc) csm[tid] = g_col[p + tid];
        __syncthreads();
        for (int idx = tid; idx < nc * HEADS; idx += 192) {
            int j = idx / HEADS, h = idx - j * HEADS;
            float e = leaky(g_as1[csm[j] * HEADS + h] + adc[h]);
            float w = __expf(e);
            wsm[idx] = w;
            atomicAdd(&den[h], w);
        }
        __syncthreads();
        int j = 0;
        for (; j + 1 < nc; j += 2) {
            const __half2* hrA = H1 + (size_t)csm[j] * NP1_2;
            const __half2* hrB = H1 + (size_t)csm[j + 1] * NP1_2;
            __half2 ra0 = hrA[i0], ra1 = hrA[i1];
            __half2 rb0 = hrB[i0], rb1 = hrB[i1];
            const float* wA = wsm + j * HEADS;
            const float* wB = wsm + (j + 1) * HEADS;
            float2 a0 = __half22float2(ra0), a1 = __half22float2(ra1);
            float2 b0 = __half22float2(rb0), b1 = __half22float2(rb1);
            acc0.x += a0.x * wA[h00] + b0.x * wB[h00];
            acc0.y += a0.y * wA[h01] + b0.y * wB[h01];
            acc1.x += a1.x * wA[h10] + b1.x * wB[h10];
            acc1.y += a1.y * wA[h11] + b1.y * wB[h11];
        }
        if (j < nc) {
            const __half2* hr = H1 + (size_t)csm[j] * NP1_2;
            const float* wj = wsm + j * HEADS;
            float2 v0 = __half22float2(hr[i0]);
            float2 v1 = __half22float2(hr[i1]);
            acc0.x += v0.x * wj[h00];
            acc0.y += v0.y * wj[h01];
            acc1.x += v1.x * wj[h10];
            acc1.y += v1.y * wj[h11];
        }
    }
    __syncthreads();
    __half2* orow = (__half2*)(g_out1h + (size_t)d * NP1);
    {
        float vx = acc0.x / (den[h00] + 1e-16f) + b1[c0];
        float vy = acc0.y / (den[h01] + 1e-16f) + b1[c0 + 1];
        vx = vx > 0.f ? vx : __expf(vx) - 1.f;
        vy = vy > 0.f ? vy : __expf(vy) - 1.f;
        orow[i0] = __floats2half2_rn(vx, vy);
    }
    if (c1 < HF) {
        float vx = acc1.x / (den[h10] + 1e-16f) + b1[c1];
        float vy = acc1.y / (den[h11] + 1e-16f) + b1[c1 + 1];
        vx = vx > 0.f ? vx : __expf(vx) - 1.f;
        vy = vy > 0.f ? vy : __expf(vy) - 1.f;
        orow[i1] = __floats2half2_rn(vx, vy);
    } else {
        orow[i1] = __floats2half2_rn(0.f, 0.f);
    }
}

// ---------------- layer-2 aggregation + ReLU + graph max-pool ----------------
#define CAP2 128
__global__ __launch_bounds__(128) void agg2_kernel(
    const float* __restrict__ b2, const int* __restrict__ batch) {
    int d = blockIdx.x;
    int tid = threadIdx.x;
    __shared__ int   csm[CAP2];
    __shared__ float wsm[CAP2];
    __shared__ float den;
    if (tid == 0) den = 0.f;
    float ad = g_ad2[d];
    int start = g_rowptr[d], end = g_rowptr[d + 1];
    float acc = 0.f;
    for (int p = start; p < end; p += CAP2) {
        int nc = min(CAP2, end - p);
        __syncthreads();
        if (tid < nc) {
            int s = g_col[p + tid];
            csm[tid] = s;
            float w = __expf(leaky(g_as2[s] + ad));
            wsm[tid] = w;
            atomicAdd(&den, w);
        }
        __syncthreads();
        int j = 0;
        for (; j + 1 < nc; j += 2) {
            float vA = __half2float(g_h2h[(size_t)csm[j] * OUT_DIM + tid]);
            float vB = __half2float(g_h2h[(size_t)csm[j + 1] * OUT_DIM + tid]);
            acc += vA * wsm[j] + vB * wsm[j + 1];
        }
        if (j < nc)
            acc += __half2float(g_h2h[(size_t)csm[j] * OUT_DIM + tid]) * wsm[j];
    }
    __syncthreads();
    float v = acc / (den + 1e-16f) + b2[tid];
    v = v > 0.f ? v : 0.f;
    int gi = batch[d];
    atomicMax((int*)&g_pool[gi * OUT_DIM + tid], __float_as_int(v));
}

// ---------------- head: relu(pool @ Wg + bg) ---------------------------------
__global__ __launch_bounds__(128) void final_kernel(
    const float* __restrict__ Wg, const float* __restrict__ bg,
    float* __restrict__ out) {
    __shared__ float gr[OUT_DIM];
    int gi = blockIdx.x, j = threadIdx.x;
    gr[j] = g_pool[gi * OUT_DIM + j];
    __syncthreads();
    float acc = bg[j];
    #pragma unroll 8
    for (int k = 0; k < OUT_DIM; k++)
        acc += gr[k] * Wg[k * OUT_DIM + j];
    out[gi * OUT_DIM + j] = acc > 0.f ? acc : 0.f;
}

// ---------------- launch ------------------------------------------------------
extern "C" void kernel_launch(void* const* d_in, const int* in_sizes, int n_in,
                              void* d_out, int out_size) {
    const float* x      = (const float*)d_in[0];
    const int*   ei     = (const int*)  d_in[1];
    const int*   batch  = (const int*)  d_in[2];
    const float* W1     = (const float*)d_in[3];
    const float* a_src1 = (const float*)d_in[4];
    const float* a_dst1 = (const float*)d_in[5];
    const float* b1     = (const float*)d_in[6];
    const float* W2     = (const float*)d_in[7];
    const float* a_src2 = (const float*)d_in[8];
    const float* a_dst2 = (const float*)d_in[9];
    const float* b2     = (const float*)d_in[10];
    const float* Wg     = (const float*)d_in[11];
    const float* bg     = (const float*)d_in[12];
    float* out = (float*)d_out;

    __half *p_xh, *p_W1h, *p_W2h, *p_h1h, *p_out1h, *p_h2h;
    cudaGetSymbolAddress((void**)&p_xh,    g_xh);
    cudaGetSymbolAddress((void**)&p_W1h,   g_W1h);
    cudaGetSymbolAddress((void**)&p_W2h,   g_W2h);
    cudaGetSymbolAddress((void**)&p_h1h,   g_h1h);
    cudaGetSymbolAddress((void**)&p_out1h, g_out1h);
    cudaGetSymbolAddress((void**)&p_h2h,   g_h2h);

    const int TB = 256;
    auto nb = [](long n, int t) { return (int)((n + t - 1) / t); };

    pad_all<<<nb(PAD_TOTAL, TB), TB>>>(x, W1, W2);
    deg_count<<<nb(ET, TB), TB>>>(ei);
    attw1_kernel<<<nb(F_IN * HEADS, TB), TB>>>(W1, a_src1, a_dst1);

    // gemm1: h1 = xh @ W1h  (fp16 TC, cp.async pipelined)
    {
        dim3 g(NP1 / TBN, M_PAD / TBM);
        gemm_h<<<g, 256>>>(p_xh, p_W1h, p_h1h, M_PAD, NP1, KP1);
    }

    // CSR: multi-block scan
    scan_part<<<NBLK, SCAN_B>>>();
    scan_top<<<1, 128>>>();
    scan_down<<<NBLK, SCAN_B>>>();
    scatter_ids<<<nb(ET, TB), TB>>>(ei);

    // layer 1
    alpha1_kernel<<<nb((long)N_NODES * HEADS, TB), TB>>>(x);
    agg1_kernel<<<N_NODES, 192>>>(b1);

    // gemm2: h2 = out1 @ W2h
    {
        dim3 g(OUT_DIM / TBN, M_PAD / TBM);
        gemm_h<<<g, 256>>>(p_out1h, p_W2h, p_h2h, M_PAD, OUT_DIM, NP1);
    }

    // layer 2
    alpha2_kernel<<<nb((long)N_NODES * 32, TB), TB>>>(a_src2, a_dst2);
    agg2_kernel<<<N_NODES, 128>>>(b2, batch);

    final_kernel<<<N_GRAPHS, OUT_DIM>>>(Wg, bg, out);
}